// round 11
// baseline (speedup 1.0000x reference)
#include <cuda_runtime.h>
#include <cuda_bf16.h>
#include <cstdint>

// Problem constants
#define NE  8
#define NH  1024
#define NI  2816
#define NTK 2
#define NT  2048
#define NA  (NT * NTK)
#define NW  (NE * NH * NI)

// smem strides (bf16 elements), padded for conflict-free ldmatrix
#define A_STR  40    // 32 + 8
#define B1_STR 72    // 64 + 8
#define B2_STR 136   // 128 + 8

// -------- scratch (static device globals) --------
__device__ int g_cnt[NE];
__device__ int g_off[NE];
__device__ int g_tok[NA];
__device__ int g_pos[NA];
__device__ __align__(16) uint16_t g_xhi[NT * NH];
__device__ __align__(16) uint16_t g_xlo[NT * NH];
__device__ __align__(16) uint16_t g_wg_hi[NW], g_wg_lo[NW];
__device__ __align__(16) uint16_t g_wu_hi[NW], g_wu_lo[NW];
__device__ __align__(16) uint16_t g_wd_hi[NW], g_wd_lo[NW];
__device__ __align__(16) uint16_t g_act_hi[(size_t)NA * NI];
__device__ __align__(16) uint16_t g_act_lo[(size_t)NA * NI];
__device__ __align__(16) float    g_y[(size_t)NA * NH];

// ---------------- helpers ----------------
__device__ __forceinline__ uint32_t smem_u32(const void* p) {
    uint32_t a;
    asm("{ .reg .u64 t; cvta.to.shared.u64 t, %1; cvt.u32.u64 %0, t; }" : "=r"(a) : "l"(p));
    return a;
}
__device__ __forceinline__ void cpa16(uint32_t s, const void* g) {
    asm volatile("cp.async.cg.shared.global [%0], [%1], 16;" :: "r"(s), "l"(g));
}
__device__ __forceinline__ void cpa_commit() {
    asm volatile("cp.async.commit_group;" ::: "memory");
}
__device__ __forceinline__ void cpa_wait0() {
    asm volatile("cp.async.wait_group 0;" ::: "memory");
}
__device__ __forceinline__ void ldsm_x4(uint32_t* r, uint32_t a) {
    asm volatile("ldmatrix.sync.aligned.m8n8.x4.shared.b16 {%0,%1,%2,%3}, [%4];"
                 : "=r"(r[0]), "=r"(r[1]), "=r"(r[2]), "=r"(r[3]) : "r"(a));
}
__device__ __forceinline__ void ldsm_x2t(uint32_t* r, uint32_t a) {
    asm volatile("ldmatrix.sync.aligned.m8n8.x2.trans.shared.b16 {%0,%1}, [%2];"
                 : "=r"(r[0]), "=r"(r[1]) : "r"(a));
}
__device__ __forceinline__ void mma16816(float* d, const uint32_t* a, const uint32_t* b) {
    asm volatile("mma.sync.aligned.m16n8k16.row.col.f32.bf16.bf16.f32 "
                 "{%0,%1,%2,%3}, {%4,%5,%6,%7}, {%8,%9}, {%0,%1,%2,%3};"
                 : "+f"(d[0]), "+f"(d[1]), "+f"(d[2]), "+f"(d[3])
                 : "r"(a[0]), "r"(a[1]), "r"(a[2]), "r"(a[3]), "r"(b[0]), "r"(b[1]));
}
// fast split: hi = truncated-bf16 (exact top 16 bits), lo = rn-bf16 of residual
__device__ __forceinline__ void fsplit2(float x0, float x1, uint32_t& hi, uint32_t& lo) {
    uint32_t u0 = __float_as_uint(x0), u1 = __float_as_uint(x1);
    hi = __byte_perm(u0, u1, 0x7632);
    float r0 = x0 - __uint_as_float(u0 & 0xFFFF0000u);
    float r1 = x1 - __uint_as_float(u1 & 0xFFFF0000u);
    __nv_bfloat162 p = __floats2bfloat162_rn(r0, r1);
    lo = *(uint32_t*)&p;
}

// ---------------- launch 0: routing ----------------
__global__ void k_route(const int* __restrict__ idx) {
    __shared__ int sc[NE], scur[NE];
    int tid = threadIdx.x;
    if (tid < NE) sc[tid] = 0;
    __syncthreads();
    for (int i = tid; i < NA; i += 1024) atomicAdd(&sc[idx[i]], 1);
    __syncthreads();
    if (tid == 0) {
        int s = 0;
        for (int e = 0; e < NE; e++) { g_cnt[e] = sc[e]; g_off[e] = s; scur[e] = s; s += sc[e]; }
    }
    __syncthreads();
    for (int i = tid; i < NA; i += 1024) {
        int e = idx[i];
        int p = atomicAdd(&scur[e], 1);
        g_tok[p] = i / NTK;
        g_pos[i] = p;
    }
}

// ---------------- launch 1: split X ----------------
__global__ void k_split_x(const float* __restrict__ hs) {
    int i = blockIdx.x * blockDim.x + threadIdx.x;
    size_t base = (size_t)i * 8;
    float4 v0 = ((const float4*)(hs + base))[0];
    float4 v1 = ((const float4*)(hs + base))[1];
    float v[8] = {v0.x, v0.y, v0.z, v0.w, v1.x, v1.y, v1.z, v1.w};
    uint32_t h[4], l[4];
#pragma unroll
    for (int p = 0; p < 4; p++) fsplit2(v[2 * p], v[2 * p + 1], h[p], l[p]);
    *(uint4*)&g_xhi[base] = make_uint4(h[0], h[1], h[2], h[3]);
    *(uint4*)&g_xlo[base] = make_uint4(l[0], l[1], l[2], l[3]);
}

// ---------------- launches 2-4: split weights ----------------
__global__ void k_split_w(const float* __restrict__ src,
                          uint16_t* __restrict__ dhi, uint16_t* __restrict__ dlo) {
    size_t i = (size_t)(blockIdx.x * blockDim.x + threadIdx.x) * 8;
    float4 v0 = ((const float4*)(src + i))[0];
    float4 v1 = ((const float4*)(src + i))[1];
    float v[8] = {v0.x, v0.y, v0.z, v0.w, v1.x, v1.y, v1.z, v1.w};
    uint32_t h[4], l[4];
#pragma unroll
    for (int p = 0; p < 4; p++) fsplit2(v[2 * p], v[2 * p + 1], h[p], l[p]);
    *(uint4*)&dhi[i] = make_uint4(h[0], h[1], h[2], h[3]);
    *(uint4*)&dlo[i] = make_uint4(l[0], l[1], l[2], l[3]);
}

// ---------------- launch 5: GEMM1 act = silu(X@Wg)*(X@Wu) ----------------
#define STG1 38912
__global__ __launch_bounds__(256, 2)
void k_gate_up() {
    const int e   = blockIdx.z;
    const int cnt = g_cnt[e];
    const int m0  = blockIdx.x * 128;
    if (m0 >= cnt) return;
    const int seg = g_off[e];
    const int c0  = blockIdx.y * 64;

    extern __shared__ char smem[];
    __shared__ int rows[128];

    const int tid = threadIdx.x;
    const int lane = tid & 31, wid = tid >> 5;
    const int wm = wid & 3, wn = wid >> 2;

    if (tid < 128) rows[tid] = (m0 + tid < cnt) ? g_tok[seg + m0 + tid] : g_tok[seg];
    __syncthreads();

    const int am = tid >> 1, ak = (tid & 1) * 16;
    const int arow = rows[am];
    const uint16_t* pxh = g_xhi + (size_t)arow * NH + ak;
    const uint16_t* pxl = g_xlo + (size_t)arow * NH + ak;

    const int half = tid >> 7;
    const int bt = tid & 127;
    const int bk = bt >> 2, bn = (bt & 3) * 16;
    const size_t boff = (size_t)e * NH * NI + (size_t)bk * NI + c0 + bn;
    const uint16_t* pbh = (half ? g_wu_hi : g_wg_hi) + boff;
    const uint16_t* pbl = (half ? g_wu_lo : g_wg_lo) + boff;

    const uint32_t sb = smem_u32(smem);
    const uint32_t OAH = 0, OAL = 10240, OGH = 20480, OGL = 25088, OUH = 29696, OUL = 34304;
    const uint32_t obh = half ? OUH : OGH;
    const uint32_t obl = half ? OUL : OGL;
    const uint32_t dA  = sb + OAH + (uint32_t)(am * A_STR + ak) * 2;
    const uint32_t dAl = sb + OAL + (uint32_t)(am * A_STR + ak) * 2;
    const uint32_t dB  = sb + obh + (uint32_t)(bk * B1_STR + bn) * 2;
    const uint32_t dBl = sb + obl + (uint32_t)(bk * B1_STR + bn) * 2;

    float dg[2][4][4], du[2][4][4];
#pragma unroll
    for (int i = 0; i < 2; i++)
#pragma unroll
        for (int j = 0; j < 4; j++)
#pragma unroll
            for (int q = 0; q < 4; q++) { dg[i][j][q] = 0.f; du[i][j][q] = 0.f; }

#define LOAD1(st, c)                                                     \
    do {                                                                 \
        const uint16_t* _ah = pxh + (c) * 32;                            \
        const uint16_t* _al = pxl + (c) * 32;                            \
        const uint16_t* _bh = pbh + (size_t)(c) * 32 * NI;               \
        const uint16_t* _bl = pbl + (size_t)(c) * 32 * NI;               \
        cpa16(dA + (st), _ah);      cpa16(dA + (st) + 16, _ah + 8);      \
        cpa16(dAl + (st), _al);     cpa16(dAl + (st) + 16, _al + 8);     \
        cpa16(dB + (st), _bh);      cpa16(dB + (st) + 16, _bh + 8);      \
        cpa16(dBl + (st), _bl);     cpa16(dBl + (st) + 16, _bl + 8);     \
    } while (0)

    LOAD1(0, 0);
    cpa_commit();
    cpa_wait0();
    __syncthreads();

    const int NC = NH / 32;
    for (int c = 0; c < NC; c++) {
        const uint32_t cur = (uint32_t)(c & 1) * STG1;
        const uint32_t nxt = cur ^ STG1;
        if (c + 1 < NC) { LOAD1(nxt, c + 1); cpa_commit(); }

#pragma unroll
        for (int ks = 0; ks < 2; ks++) {
            const int k16 = ks * 16;
            uint32_t ah[2][4], al[2][4];
#pragma unroll
            for (int i = 0; i < 2; i++) {
                int row = wm * 32 + i * 16 + (lane & 15);
                int col = k16 + (lane >> 4) * 8;
                uint32_t off = (uint32_t)(row * A_STR + col) * 2;
                ldsm_x4(ah[i], sb + cur + OAH + off);
                ldsm_x4(al[i], sb + cur + OAL + off);
            }
#pragma unroll
            for (int j = 0; j < 4; j++) {
                int n = wn * 32 + j * 8;
                uint32_t off = (uint32_t)((k16 + (lane & 15)) * B1_STR + n) * 2;
                uint32_t gh[2], gl[2], uh[2], ul[2];
                ldsm_x2t(gh, sb + cur + OGH + off);
                ldsm_x2t(gl, sb + cur + OGL + off);
                ldsm_x2t(uh, sb + cur + OUH + off);
                ldsm_x2t(ul, sb + cur + OUL + off);
                // term-major emission: same-accumulator distance = 4
                mma16816(dg[0][j], ah[0], gh);
                mma16816(dg[1][j], ah[1], gh);
                mma16816(du[0][j], ah[0], uh);
                mma16816(du[1][j], ah[1], uh);
                mma16816(dg[0][j], ah[0], gl);
                mma16816(dg[1][j], ah[1], gl);
                mma16816(du[0][j], ah[0], ul);
                mma16816(du[1][j], ah[1], ul);
                mma16816(dg[0][j], al[0], gh);
                mma16816(dg[1][j], al[1], gh);
                mma16816(du[0][j], al[0], uh);
                mma16816(du[1][j], al[1], uh);
            }
        }
        if (c + 1 < NC) cpa_wait0();
        __syncthreads();
    }
#undef LOAD1

    // epilogue: silu(g)*u -> act hi/lo
#pragma unroll
    for (int i = 0; i < 2; i++)
#pragma unroll
        for (int h2 = 0; h2 < 2; h2++) {
            int m = m0 + wm * 32 + i * 16 + h2 * 8 + (lane >> 2);
            if (m < cnt) {
                size_t rowb = (size_t)(seg + m) * NI + c0 + wn * 32 + (lane & 3) * 2;
#pragma unroll
                for (int j = 0; j < 4; j++) {
                    float g0 = dg[i][j][h2 * 2], g1 = dg[i][j][h2 * 2 + 1];
                    float u0 = du[i][j][h2 * 2], u1 = du[i][j][h2 * 2 + 1];
                    float r0 = g0 / (1.f + __expf(-g0)) * u0;
                    float r1 = g1 / (1.f + __expf(-g1)) * u1;
                    uint32_t hh, ll;
                    fsplit2(r0, r1, hh, ll);
                    *(uint32_t*)&g_act_hi[rowb + j * 8] = hh;
                    *(uint32_t*)&g_act_lo[rowb + j * 8] = ll;
                }
            }
        }
}

// ---------------- launch 6: GEMM2 y = act @ Wd ----------------
#define STG2 37888
__global__ __launch_bounds__(256, 2)
void k_down() {
    const int e   = blockIdx.z;
    const int cnt = g_cnt[e];
    const int m0  = blockIdx.x * 128;
    if (m0 >= cnt) return;
    const int seg = g_off[e];
    const int h0  = blockIdx.y * 128;

    extern __shared__ char smem[];

    const int tid = threadIdx.x;
    const int lane = tid & 31, wid = tid >> 5;
    const int wm = wid & 3, wn = wid >> 2;

    const int am = tid >> 1, ak = (tid & 1) * 16;
    const int aslot = seg + ((m0 + am < cnt) ? (m0 + am) : 0);
    const uint16_t* pah = g_act_hi + (size_t)aslot * NI + ak;
    const uint16_t* pal = g_act_lo + (size_t)aslot * NI + ak;

    const int bk = tid >> 3, bn = (tid & 7) * 16;
    const size_t boff = (size_t)e * NI * NH + (size_t)bk * NH + h0 + bn;
    const uint16_t* pbh = g_wd_hi + boff;
    const uint16_t* pbl = g_wd_lo + boff;

    const uint32_t sb = smem_u32(smem);
    const uint32_t OAH = 0, OAL = 10240, OBH = 20480, OBL = 29184;
    const uint32_t dA  = sb + OAH + (uint32_t)(am * A_STR + ak) * 2;
    const uint32_t dAl = sb + OAL + (uint32_t)(am * A_STR + ak) * 2;
    const uint32_t dB  = sb + OBH + (uint32_t)(bk * B2_STR + bn) * 2;
    const uint32_t dBl = sb + OBL + (uint32_t)(bk * B2_STR + bn) * 2;

    float acc[2][8][4];
#pragma unroll
    for (int i = 0; i < 2; i++)
#pragma unroll
        for (int j = 0; j < 8; j++)
#pragma unroll
            for (int q = 0; q < 4; q++) acc[i][j][q] = 0.f;

#define LOAD2(st, c)                                                     \
    do {                                                                 \
        const uint16_t* _ah = pah + (c) * 32;                            \
        const uint16_t* _al = pal + (c) * 32;                            \
        const uint16_t* _bh = pbh + (size_t)(c) * 32 * NH;               \
        const uint16_t* _bl = pbl + (size_t)(c) * 32 * NH;               \
        cpa16(dA + (st), _ah);      cpa16(dA + (st) + 16, _ah + 8);      \
        cpa16(dAl + (st), _al);     cpa16(dAl + (st) + 16, _al + 8);     \
        cpa16(dB + (st), _bh);      cpa16(dB + (st) + 16, _bh + 8);      \
        cpa16(dBl + (st), _bl);     cpa16(dBl + (st) + 16, _bl + 8);     \
    } while (0)

    LOAD2(0, 0);
    cpa_commit();
    cpa_wait0();
    __syncthreads();

    const int NC = NI / 32;
    for (int c = 0; c < NC; c++) {
        const uint32_t cur = (uint32_t)(c & 1) * STG2;
        const uint32_t nxt = cur ^ STG2;
        if (c + 1 < NC) { LOAD2(nxt, c + 1); cpa_commit(); }

#pragma unroll
        for (int ks = 0; ks < 2; ks++) {
            const int k16 = ks * 16;
            uint32_t ah[2][4], al[2][4];
#pragma unroll
            for (int i = 0; i < 2; i++) {
                int row = wm * 32 + i * 16 + (lane & 15);
                int col = k16 + (lane >> 4) * 8;
                uint32_t off = (uint32_t)(row * A_STR + col) * 2;
                ldsm_x4(ah[i], sb + cur + OAH + off);
                ldsm_x4(al[i], sb + cur + OAL + off);
            }
            // process j in pairs: same-accumulator distance = 4
#pragma unroll
            for (int jp = 0; jp < 4; jp++) {
                const int j0 = jp * 2, j1 = jp * 2 + 1;
                int n0 = wn * 64 + j0 * 8, n1 = wn * 64 + j1 * 8;
                uint32_t o0 = (uint32_t)((k16 + (lane & 15)) * B2_STR + n0) * 2;
                uint32_t o1 = (uint32_t)((k16 + (lane & 15)) * B2_STR + n1) * 2;
                uint32_t bh0[2], bl0[2], bh1[2], bl1[2];
                ldsm_x2t(bh0, sb + cur + OBH + o0);
                ldsm_x2t(bl0, sb + cur + OBL + o0);
                ldsm_x2t(bh1, sb + cur + OBH + o1);
                ldsm_x2t(bl1, sb + cur + OBL + o1);
                mma16816(acc[0][j0], ah[0], bh0);
                mma16816(acc[1][j0], ah[1], bh0);
                mma16816(acc[0][j1], ah[0], bh1);
                mma16816(acc[1][j1], ah[1], bh1);
                mma16816(acc[0][j0], ah[0], bl0);
                mma16816(acc[1][j0], ah[1], bl0);
                mma16816(acc[0][j1], ah[0], bl1);
                mma16816(acc[1][j1], ah[1], bl1);
                mma16816(acc[0][j0], al[0], bh0);
                mma16816(acc[1][j0], al[1], bh0);
                mma16816(acc[0][j1], al[0], bh1);
                mma16816(acc[1][j1], al[1], bh1);
            }
        }
        if (c + 1 < NC) cpa_wait0();
        __syncthreads();
    }
#undef LOAD2

#pragma unroll
    for (int i = 0; i < 2; i++)
#pragma unroll
        for (int h2 = 0; h2 < 2; h2++) {
            int m = m0 + wm * 32 + i * 16 + h2 * 8 + (lane >> 2);
            if (m < cnt) {
                float* op = g_y + (size_t)(seg + m) * NH + h0 + wn * 64 + (lane & 3) * 2;
#pragma unroll
                for (int j = 0; j < 8; j++)
                    *(float2*)(op + j * 8) = make_float2(acc[i][j][h2 * 2], acc[i][j][h2 * 2 + 1]);
            }
        }
}

// ---------------- launch 7: combine ----------------
__global__ void k_combine(const float* __restrict__ val, float* __restrict__ out) {
    int i = blockIdx.x * blockDim.x + threadIdx.x;
    if (i >= NT * (NH / 4)) return;
    int t  = i / (NH / 4);
    int h4 = i - t * (NH / 4);
    float4 r = make_float4(0.f, 0.f, 0.f, 0.f);
#pragma unroll
    for (int k = 0; k < NTK; k++) {
        int   p = g_pos[t * NTK + k];
        float w = val[t * NTK + k];
        float4 y = *(const float4*)&g_y[(size_t)p * NH + h4 * 4];
        r.x += w * y.x; r.y += w * y.y; r.z += w * y.z; r.w += w * y.w;
    }
    *(float4*)&out[(size_t)t * NH + h4 * 4] = r;
}

// ---------------- launch ----------------
extern "C" void kernel_launch(void* const* d_in, const int* in_sizes, int n_in,
                              void* d_out, int out_size) {
    const float* hs  = (const float*)d_in[0];
    const int*   idx = (const int*)d_in[1];
    const float* val = (const float*)d_in[2];
    const float* wg  = (const float*)d_in[3];
    const float* wu  = (const float*)d_in[4];
    const float* wd  = (const float*)d_in[5];
    float*       out = (float*)d_out;
    (void)in_sizes; (void)n_in; (void)out_size;

    cudaFuncSetAttribute(k_gate_up, cudaFuncAttributeMaxDynamicSharedMemorySize, 2 * STG1);
    cudaFuncSetAttribute(k_down,    cudaFuncAttributeMaxDynamicSharedMemorySize, 2 * STG2);

    uint16_t *wg_hi, *wg_lo, *wu_hi, *wu_lo, *wd_hi, *wd_lo;
    cudaGetSymbolAddress((void**)&wg_hi, g_wg_hi);
    cudaGetSymbolAddress((void**)&wg_lo, g_wg_lo);
    cudaGetSymbolAddress((void**)&wu_hi, g_wu_hi);
    cudaGetSymbolAddress((void**)&wu_lo, g_wu_lo);
    cudaGetSymbolAddress((void**)&wd_hi, g_wd_hi);
    cudaGetSymbolAddress((void**)&wd_lo, g_wd_lo);

    k_route<<<1, 1024>>>(idx);                                  // 0
    k_split_x<<<NT * NH / 8 / 256, 256>>>(hs);                  // 1
    k_split_w<<<NW / 8 / 256, 256>>>(wg, wg_hi, wg_lo);         // 2
    k_split_w<<<NW / 8 / 256, 256>>>(wu, wu_hi, wu_lo);         // 3
    k_split_w<<<NW / 8 / 256, 256>>>(wd, wd_hi, wd_lo);         // 4

    dim3 g1(NA / 128, NI / 64, NE);                             // 5
    k_gate_up<<<g1, 256, 2 * STG1>>>();

    dim3 g2(NA / 128, NH / 128, NE);                            // 6
    k_down<<<g2, 256, 2 * STG2>>>();

    k_combine<<<(NT * (NH / 4) + 255) / 256, 256>>>(val, out);  // 7
}

// round 15
// speedup vs baseline: 1.0237x; 1.0237x over previous
#include <cuda_runtime.h>
#include <cuda_bf16.h>
#include <cstdint>

// Problem constants
#define NE  8
#define NH  1024
#define NI  2816
#define NTK 2
#define NT  2048
#define NA  (NT * NTK)
#define NW  (NE * NH * NI)

// smem strides (bf16 elements); rows are 16B-multiples (cp.async) and
// ldmatrix conflict-free (proven R10 values)
#define A_STR  40    // 32 + 8  -> 80B rows
#define B1_STR 72    // 64 + 8  -> 144B rows
#define B2_STR 136   // 128 + 8 -> 272B rows

// stage sizes (bytes)
#define ASTG  20480              // A hi (10240) + A lo (10240)
#define B1STG 18432              // 4 x 4608 (gh, gl, uh, ul)
#define B2STG 17408              // 2 x 8704 (bh, bl)
#define OB1   40960              // B region base (after 2 A stages)
#define OB2   40960

// -------- scratch (static device globals) --------
__device__ int g_cnt[NE];
__device__ int g_off[NE];
__device__ int g_tok[NA];
__device__ int g_pos[NA];
__device__ __align__(16) uint16_t g_xhi[NT * NH];
__device__ __align__(16) uint16_t g_xlo[NT * NH];
__device__ __align__(16) uint16_t g_wg_hi[NW], g_wg_lo[NW];
__device__ __align__(16) uint16_t g_wu_hi[NW], g_wu_lo[NW];
__device__ __align__(16) uint16_t g_wd_hi[NW], g_wd_lo[NW];
__device__ __align__(16) uint16_t g_act_hi[(size_t)NA * NI];
__device__ __align__(16) uint16_t g_act_lo[(size_t)NA * NI];
__device__ __align__(16) float    g_y[(size_t)NA * NH];

// ---------------- helpers ----------------
__device__ __forceinline__ uint32_t smem_u32(const void* p) {
    uint32_t a;
    asm("{ .reg .u64 t; cvta.to.shared.u64 t, %1; cvt.u32.u64 %0, t; }" : "=r"(a) : "l"(p));
    return a;
}
__device__ __forceinline__ void cpa16(uint32_t s, const void* g) {
    asm volatile("cp.async.cg.shared.global [%0], [%1], 16;" :: "r"(s), "l"(g));
}
__device__ __forceinline__ void cpa_commit() {
    asm volatile("cp.async.commit_group;" ::: "memory");
}
__device__ __forceinline__ void cpa_wait0() {
    asm volatile("cp.async.wait_group 0;" ::: "memory");
}
__device__ __forceinline__ void cpa_wait1() {
    asm volatile("cp.async.wait_group 1;" ::: "memory");
}
__device__ __forceinline__ void ldsm_x4(uint32_t* r, uint32_t a) {
    asm volatile("ldmatrix.sync.aligned.m8n8.x4.shared.b16 {%0,%1,%2,%3}, [%4];"
                 : "=r"(r[0]), "=r"(r[1]), "=r"(r[2]), "=r"(r[3]) : "r"(a));
}
__device__ __forceinline__ void ldsm_x2t(uint32_t* r, uint32_t a) {
    asm volatile("ldmatrix.sync.aligned.m8n8.x2.trans.shared.b16 {%0,%1}, [%2];"
                 : "=r"(r[0]), "=r"(r[1]) : "r"(a));
}
__device__ __forceinline__ void mma16816(float* d, const uint32_t* a, const uint32_t* b) {
    asm volatile("mma.sync.aligned.m16n8k16.row.col.f32.bf16.bf16.f32 "
                 "{%0,%1,%2,%3}, {%4,%5,%6,%7}, {%8,%9}, {%0,%1,%2,%3};"
                 : "+f"(d[0]), "+f"(d[1]), "+f"(d[2]), "+f"(d[3])
                 : "r"(a[0]), "r"(a[1]), "r"(a[2]), "r"(a[3]), "r"(b[0]), "r"(b[1]));
}
// fast split: hi = truncated-bf16 (exact top 16 bits), lo = rn-bf16 of residual
__device__ __forceinline__ void fsplit2(float x0, float x1, uint32_t& hi, uint32_t& lo) {
    uint32_t u0 = __float_as_uint(x0), u1 = __float_as_uint(x1);
    hi = __byte_perm(u0, u1, 0x7632);
    float r0 = x0 - __uint_as_float(u0 & 0xFFFF0000u);
    float r1 = x1 - __uint_as_float(u1 & 0xFFFF0000u);
    __nv_bfloat162 p = __floats2bfloat162_rn(r0, r1);
    lo = *(uint32_t*)&p;
}

// ---------------- launch 0: routing ----------------
__global__ void k_route(const int* __restrict__ idx) {
    __shared__ int sc[NE], scur[NE];
    int tid = threadIdx.x;
    if (tid < NE) sc[tid] = 0;
    __syncthreads();
    for (int i = tid; i < NA; i += 1024) atomicAdd(&sc[idx[i]], 1);
    __syncthreads();
    if (tid == 0) {
        int s = 0;
        for (int e = 0; e < NE; e++) { g_cnt[e] = sc[e]; g_off[e] = s; scur[e] = s; s += sc[e]; }
    }
    __syncthreads();
    for (int i = tid; i < NA; i += 1024) {
        int e = idx[i];
        int p = atomicAdd(&scur[e], 1);
        g_tok[p] = i / NTK;
        g_pos[i] = p;
    }
}

// ---------------- launch 1: split X ----------------
__global__ void k_split_x(const float* __restrict__ hs) {
    int i = blockIdx.x * blockDim.x + threadIdx.x;
    size_t base = (size_t)i * 8;
    float4 v0 = ((const float4*)(hs + base))[0];
    float4 v1 = ((const float4*)(hs + base))[1];
    float v[8] = {v0.x, v0.y, v0.z, v0.w, v1.x, v1.y, v1.z, v1.w};
    uint32_t h[4], l[4];
#pragma unroll
    for (int p = 0; p < 4; p++) fsplit2(v[2 * p], v[2 * p + 1], h[p], l[p]);
    *(uint4*)&g_xhi[base] = make_uint4(h[0], h[1], h[2], h[3]);
    *(uint4*)&g_xlo[base] = make_uint4(l[0], l[1], l[2], l[3]);
}

// ---------------- launch 2: split all three weight tensors ----------------
__global__ void k_split_w3(const float* __restrict__ wg, const float* __restrict__ wu,
                           const float* __restrict__ wd) {
    const float* src;
    uint16_t *dhi, *dlo;
    if (blockIdx.y == 0)      { src = wg; dhi = g_wg_hi; dlo = g_wg_lo; }
    else if (blockIdx.y == 1) { src = wu; dhi = g_wu_hi; dlo = g_wu_lo; }
    else                      { src = wd; dhi = g_wd_hi; dlo = g_wd_lo; }
    size_t i = (size_t)(blockIdx.x * blockDim.x + threadIdx.x) * 8;
    float4 v0 = ((const float4*)(src + i))[0];
    float4 v1 = ((const float4*)(src + i))[1];
    float v[8] = {v0.x, v0.y, v0.z, v0.w, v1.x, v1.y, v1.z, v1.w};
    uint32_t h[4], l[4];
#pragma unroll
    for (int p = 0; p < 4; p++) fsplit2(v[2 * p], v[2 * p + 1], h[p], l[p]);
    *(uint4*)&dhi[i] = make_uint4(h[0], h[1], h[2], h[3]);
    *(uint4*)&dlo[i] = make_uint4(l[0], l[1], l[2], l[3]);
}

// ---------------- launch 3: GEMM1 act = silu(X@Wg)*(X@Wu) ----------------
// CTA 128m x 64n, BK=32; A double-buffered, B triple-buffered (cp.async).
__global__ __launch_bounds__(256, 2)
void k_gate_up() {
    const int e   = blockIdx.z;
    const int cnt = g_cnt[e];
    const int m0  = blockIdx.x * 128;
    if (m0 >= cnt) return;
    const int seg = g_off[e];
    const int c0  = blockIdx.y * 64;

    extern __shared__ char smem[];
    __shared__ int rows[128];

    const int tid = threadIdx.x;
    const int lane = tid & 31, wid = tid >> 5;
    const int wm = wid & 3, wn = wid >> 2;

    if (tid < 128) rows[tid] = (m0 + tid < cnt) ? g_tok[seg + m0 + tid] : g_tok[seg];
    __syncthreads();

    const int am = tid >> 1, ak = (tid & 1) * 16;
    const int arow = rows[am];
    const uint16_t* pxh = g_xhi + (size_t)arow * NH + ak;
    const uint16_t* pxl = g_xlo + (size_t)arow * NH + ak;

    const int half = tid >> 7;
    const int bt = tid & 127;
    const int bk = bt >> 2, bn = (bt & 3) * 16;
    const size_t boff = (size_t)e * NH * NI + (size_t)bk * NI + c0 + bn;
    const uint16_t* pbh = (half ? g_wu_hi : g_wg_hi) + boff;
    const uint16_t* pbl = (half ? g_wu_lo : g_wg_lo) + boff;

    const uint32_t sb = smem_u32(smem);
    // A stage internal: AH 0, AL 10240.  B stage internal: GH 0, GL 4608, UH 9216, UL 13824.
    const uint32_t obh = half ? 9216u : 0u;
    const uint32_t obl = half ? 13824u : 4608u;
    const uint32_t dAh = sb + (uint32_t)(am * A_STR + ak) * 2;
    const uint32_t dAl = dAh + 10240;
    const uint32_t dBh = sb + OB1 + obh + (uint32_t)(bk * B1_STR + bn) * 2;
    const uint32_t dBl = sb + OB1 + obl + (uint32_t)(bk * B1_STR + bn) * 2;

    float dg[2][4][4], du[2][4][4];
#pragma unroll
    for (int i = 0; i < 2; i++)
#pragma unroll
        for (int j = 0; j < 4; j++)
#pragma unroll
            for (int q = 0; q < 4; q++) { dg[i][j][q] = 0.f; du[i][j][q] = 0.f; }

#define LOADA1(st, c)                                                     \
    do {                                                                  \
        const uint16_t* _ah = pxh + (c) * 32;                             \
        const uint16_t* _al = pxl + (c) * 32;                             \
        cpa16(dAh + (st), _ah);  cpa16(dAh + (st) + 16, _ah + 8);         \
        cpa16(dAl + (st), _al);  cpa16(dAl + (st) + 16, _al + 8);         \
    } while (0)
#define LOADB1(st, c)                                                     \
    do {                                                                  \
        const uint16_t* _bh = pbh + (size_t)(c) * 32 * NI;                \
        const uint16_t* _bl = pbl + (size_t)(c) * 32 * NI;                \
        cpa16(dBh + (st), _bh);  cpa16(dBh + (st) + 16, _bh + 8);         \
        cpa16(dBl + (st), _bl);  cpa16(dBl + (st) + 16, _bl + 8);         \
    } while (0)

    const int NC = NH / 32;
    LOADA1(0, 0);         cpa_commit();
    LOADB1(0, 0);         cpa_commit();
    LOADB1(B1STG, 1);     cpa_commit();
    cpa_wait1();          // A(0), B(0) landed (B(1) may be pending)
    __syncthreads();

    int bs = 0, bn3 = 2;   // B stage of c, B stage of c+2
    for (int c = 0; c < NC; c++) {
        const uint32_t ca = (uint32_t)(c & 1) * ASTG;
        const uint32_t cb = OB1 + (uint32_t)bs * B1STG;
        if (c + 1 < NC) { LOADA1(((c + 1) & 1) * ASTG, c + 1); cpa_commit(); }
        if (c + 2 < NC) { LOADB1((uint32_t)bn3 * B1STG, c + 2); cpa_commit(); }

#pragma unroll
        for (int ks = 0; ks < 2; ks++) {
            const int k16 = ks * 16;
            uint32_t ah[2][4], al[2][4];
#pragma unroll
            for (int i = 0; i < 2; i++) {
                int row = wm * 32 + i * 16 + (lane & 15);
                int col = k16 + (lane >> 4) * 8;
                uint32_t off = (uint32_t)(row * A_STR + col) * 2;
                ldsm_x4(ah[i], sb + ca + off);
                ldsm_x4(al[i], sb + ca + 10240 + off);
            }
#pragma unroll
            for (int j = 0; j < 4; j++) {
                int n = wn * 32 + j * 8;
                uint32_t off = (uint32_t)((k16 + (lane & 15)) * B1_STR + n) * 2;
                uint32_t gh[2], gl[2], uh[2], ul[2];
                ldsm_x2t(gh, sb + cb + off);
                ldsm_x2t(gl, sb + cb + 4608 + off);
                ldsm_x2t(uh, sb + cb + 9216 + off);
                ldsm_x2t(ul, sb + cb + 13824 + off);
                mma16816(dg[0][j], ah[0], gh);
                mma16816(dg[1][j], ah[1], gh);
                mma16816(du[0][j], ah[0], uh);
                mma16816(du[1][j], ah[1], uh);
                mma16816(dg[0][j], ah[0], gl);
                mma16816(dg[1][j], ah[1], gl);
                mma16816(du[0][j], ah[0], ul);
                mma16816(du[1][j], ah[1], ul);
                mma16816(dg[0][j], al[0], gh);
                mma16816(dg[1][j], al[1], gh);
                mma16816(du[0][j], al[0], uh);
                mma16816(du[1][j], al[1], uh);
            }
        }
        if (c + 2 < NC) cpa_wait1(); else cpa_wait0();
        __syncthreads();
        bs = (bs == 2) ? 0 : bs + 1;
        bn3 = (bn3 == 2) ? 0 : bn3 + 1;
    }
#undef LOADA1
#undef LOADB1

    // epilogue: silu(g)*u -> act hi/lo
#pragma unroll
    for (int i = 0; i < 2; i++)
#pragma unroll
        for (int h2 = 0; h2 < 2; h2++) {
            int m = m0 + wm * 32 + i * 16 + h2 * 8 + (lane >> 2);
            if (m < cnt) {
                size_t rowb = (size_t)(seg + m) * NI + c0 + wn * 32 + (lane & 3) * 2;
#pragma unroll
                for (int j = 0; j < 4; j++) {
                    float g0 = dg[i][j][h2 * 2], g1 = dg[i][j][h2 * 2 + 1];
                    float u0 = du[i][j][h2 * 2], u1 = du[i][j][h2 * 2 + 1];
                    float r0 = g0 / (1.f + __expf(-g0)) * u0;
                    float r1 = g1 / (1.f + __expf(-g1)) * u1;
                    uint32_t hh, ll;
                    fsplit2(r0, r1, hh, ll);
                    *(uint32_t*)&g_act_hi[rowb + j * 8] = hh;
                    *(uint32_t*)&g_act_lo[rowb + j * 8] = ll;
                }
            }
        }
}

// ---------------- launch 4: GEMM2 y = act @ Wd ----------------
// CTA 128m x 128n, BK=32; A double-buffered, B triple-buffered.
__global__ __launch_bounds__(256, 2)
void k_down() {
    const int e   = blockIdx.z;
    const int cnt = g_cnt[e];
    const int m0  = blockIdx.x * 128;
    if (m0 >= cnt) return;
    const int seg = g_off[e];
    const int h0  = blockIdx.y * 128;

    extern __shared__ char smem[];

    const int tid = threadIdx.x;
    const int lane = tid & 31, wid = tid >> 5;
    const int wm = wid & 3, wn = wid >> 2;

    const int am = tid >> 1, ak = (tid & 1) * 16;
    const int aslot = seg + ((m0 + am < cnt) ? (m0 + am) : 0);
    const uint16_t* pah = g_act_hi + (size_t)aslot * NI + ak;
    const uint16_t* pal = g_act_lo + (size_t)aslot * NI + ak;

    const int bk = tid >> 3, bn = (tid & 7) * 16;
    const size_t boff = (size_t)e * NI * NH + (size_t)bk * NH + h0 + bn;
    const uint16_t* pbh = g_wd_hi + boff;
    const uint16_t* pbl = g_wd_lo + boff;

    const uint32_t sb = smem_u32(smem);
    const uint32_t dAh = sb + (uint32_t)(am * A_STR + ak) * 2;
    const uint32_t dAl = dAh + 10240;
    const uint32_t dBh = sb + OB2 + (uint32_t)(bk * B2_STR + bn) * 2;
    const uint32_t dBl = dBh + 8704;

    float acc[2][8][4];
#pragma unroll
    for (int i = 0; i < 2; i++)
#pragma unroll
        for (int j = 0; j < 8; j++)
#pragma unroll
            for (int q = 0; q < 4; q++) acc[i][j][q] = 0.f;

#define LOADA2(st, c)                                                     \
    do {                                                                  \
        const uint16_t* _ah = pah + (c) * 32;                             \
        const uint16_t* _al = pal + (c) * 32;                             \
        cpa16(dAh + (st), _ah);  cpa16(dAh + (st) + 16, _ah + 8);         \
        cpa16(dAl + (st), _al);  cpa16(dAl + (st) + 16, _al + 8);         \
    } while (0)
#define LOADB2(st, c)                                                     \
    do {                                                                  \
        const uint16_t* _bh = pbh + (size_t)(c) * 32 * NH;                \
        const uint16_t* _bl = pbl + (size_t)(c) * 32 * NH;                \
        cpa16(dBh + (st), _bh);  cpa16(dBh + (st) + 16, _bh + 8);         \
        cpa16(dBl + (st), _bl);  cpa16(dBl + (st) + 16, _bl + 8);         \
    } while (0)

    const int NC = NI / 32;
    LOADA2(0, 0);         cpa_commit();
    LOADB2(0, 0);         cpa_commit();
    LOADB2(B2STG, 1);     cpa_commit();
    cpa_wait1();
    __syncthreads();

    int bs = 0, bn3 = 2;
    for (int c = 0; c < NC; c++) {
        const uint32_t ca = (uint32_t)(c & 1) * ASTG;
        const uint32_t cb = OB2 + (uint32_t)bs * B2STG;
        if (c + 1 < NC) { LOADA2(((c + 1) & 1) * ASTG, c + 1); cpa_commit(); }
        if (c + 2 < NC) { LOADB2((uint32_t)bn3 * B2STG, c + 2); cpa_commit(); }

#pragma unroll
        for (int ks = 0; ks < 2; ks++) {
            const int k16 = ks * 16;
            uint32_t ah[2][4], al[2][4];
#pragma unroll
            for (int i = 0; i < 2; i++) {
                int row = wm * 32 + i * 16 + (lane & 15);
                int col = k16 + (lane >> 4) * 8;
                uint32_t off = (uint32_t)(row * A_STR + col) * 2;
                ldsm_x4(ah[i], sb + ca + off);
                ldsm_x4(al[i], sb + ca + 10240 + off);
            }
#pragma unroll
            for (int jp = 0; jp < 4; jp++) {
                const int j0 = jp * 2, j1 = jp * 2 + 1;
                int n0 = wn * 64 + j0 * 8, n1 = wn * 64 + j1 * 8;
                uint32_t o0 = (uint32_t)((k16 + (lane & 15)) * B2_STR + n0) * 2;
                uint32_t o1 = (uint32_t)((k16 + (lane & 15)) * B2_STR + n1) * 2;
                uint32_t bh0[2], bl0[2], bh1[2], bl1[2];
                ldsm_x2t(bh0, sb + cb + o0);
                ldsm_x2t(bl0, sb + cb + 8704 + o0);
                ldsm_x2t(bh1, sb + cb + o1);
                ldsm_x2t(bl1, sb + cb + 8704 + o1);
                mma16816(acc[0][j0], ah[0], bh0);
                mma16816(acc[1][j0], ah[1], bh0);
                mma16816(acc[0][j1], ah[0], bh1);
                mma16816(acc[1][j1], ah[1], bh1);
                mma16816(acc[0][j0], ah[0], bl0);
                mma16816(acc[1][j0], ah[1], bl0);
                mma16816(acc[0][j1], ah[0], bl1);
                mma16816(acc[1][j1], ah[1], bl1);
                mma16816(acc[0][j0], al[0], bh0);
                mma16816(acc[1][j0], al[1], bh0);
                mma16816(acc[0][j1], al[0], bh1);
                mma16816(acc[1][j1], al[1], bh1);
            }
        }
        if (c + 2 < NC) cpa_wait1(); else cpa_wait0();
        __syncthreads();
        bs = (bs == 2) ? 0 : bs + 1;
        bn3 = (bn3 == 2) ? 0 : bn3 + 1;
    }
#undef LOADA2
#undef LOADB2

#pragma unroll
    for (int i = 0; i < 2; i++)
#pragma unroll
        for (int h2 = 0; h2 < 2; h2++) {
            int m = m0 + wm * 32 + i * 16 + h2 * 8 + (lane >> 2);
            if (m < cnt) {
                float* op = g_y + (size_t)(seg + m) * NH + h0 + wn * 64 + (lane & 3) * 2;
#pragma unroll
                for (int j = 0; j < 8; j++)
                    *(float2*)(op + j * 8) = make_float2(acc[i][j][h2 * 2], acc[i][j][h2 * 2 + 1]);
            }
        }
}

// ---------------- launch 5: combine ----------------
__global__ void k_combine(const float* __restrict__ val, float* __restrict__ out) {
    int i = blockIdx.x * blockDim.x + threadIdx.x;
    if (i >= NT * (NH / 4)) return;
    int t  = i / (NH / 4);
    int h4 = i - t * (NH / 4);
    float4 r = make_float4(0.f, 0.f, 0.f, 0.f);
#pragma unroll
    for (int k = 0; k < NTK; k++) {
        int   p = g_pos[t * NTK + k];
        float w = val[t * NTK + k];
        float4 y = *(const float4*)&g_y[(size_t)p * NH + h4 * 4];
        r.x += w * y.x; r.y += w * y.y; r.z += w * y.z; r.w += w * y.w;
    }
    *(float4*)&out[(size_t)t * NH + h4 * 4] = r;
}

// ---------------- launch ----------------
extern "C" void kernel_launch(void* const* d_in, const int* in_sizes, int n_in,
                              void* d_out, int out_size) {
    const float* hs  = (const float*)d_in[0];
    const int*   idx = (const int*)d_in[1];
    const float* val = (const float*)d_in[2];
    const float* wg  = (const float*)d_in[3];
    const float* wu  = (const float*)d_in[4];
    const float* wd  = (const float*)d_in[5];
    float*       out = (float*)d_out;
    (void)in_sizes; (void)n_in; (void)out_size;

    const int SM1 = 2 * ASTG + 3 * B1STG;   // 96256
    const int SM2 = 2 * ASTG + 3 * B2STG;   // 93184
    cudaFuncSetAttribute(k_gate_up, cudaFuncAttributeMaxDynamicSharedMemorySize, SM1);
    cudaFuncSetAttribute(k_down,    cudaFuncAttributeMaxDynamicSharedMemorySize, SM2);

    k_route<<<1, 1024>>>(idx);                                  // 0
    k_split_x<<<NT * NH / 8 / 256, 256>>>(hs);                  // 1
    dim3 gw(NW / 8 / 256, 3);
    k_split_w3<<<gw, 256>>>(wg, wu, wd);                        // 2

    dim3 g1(NA / 128, NI / 64, NE);                             // 3 (profiled slot)
    k_gate_up<<<g1, 256, SM1>>>();

    dim3 g2(NA / 128, NH / 128, NE);                            // 4
    k_down<<<g2, 256, SM2>>>();

    k_combine<<<(NT * (NH / 4) + 255) / 256, 256>>>(val, out);  // 5
}

// round 17
// speedup vs baseline: 1.3481x; 1.3169x over previous
#include <cuda_runtime.h>
#include <cuda_fp16.h>
#include <cstdint>

// Problem constants
#define NE  8
#define NH  1024
#define NI  2816
#define NTK 2
#define NT  2048
#define NA  (NT * NTK)
#define NW  (NE * NH * NI)

// smem strides (fp16 elements); rows are 16B-multiples (cp.async) and
// ldmatrix conflict-free
#define A_STR  40    // 32 + 8  -> 80B rows
#define B1_STR 72    // 64 + 8  -> 144B rows
#define B2_STR 136   // 128 + 8 -> 272B rows

// stage sizes (bytes)
#define ASTG  20480              // A hi (10240) + A lo (10240)
#define B1STG 9216               // 2 x 4608 (gate hi, up hi)
#define B2STG 8704               // 1 x 8704 (wd hi)
#define OB1   40960              // B region base (after 2 A stages)
#define OB2   40960

// -------- scratch (static device globals) --------
__device__ int g_cnt[NE];
__device__ int g_off[NE];
__device__ int g_tok[NA];
__device__ int g_pos[NA];
__device__ __align__(16) uint16_t g_xhi[NT * NH];
__device__ __align__(16) uint16_t g_xlo[NT * NH];
__device__ __align__(16) uint16_t g_wg_h[NW];     // fp16 weights, 46MB each
__device__ __align__(16) uint16_t g_wu_h[NW];
__device__ __align__(16) uint16_t g_wd_h[NW];
__device__ __align__(16) uint16_t g_act_hi[(size_t)NA * NI];
__device__ __align__(16) uint16_t g_act_lo[(size_t)NA * NI];
__device__ __align__(16) float    g_y[(size_t)NA * NH];

// ---------------- helpers ----------------
__device__ __forceinline__ uint32_t smem_u32(const void* p) {
    uint32_t a;
    asm("{ .reg .u64 t; cvta.to.shared.u64 t, %1; cvt.u32.u64 %0, t; }" : "=r"(a) : "l"(p));
    return a;
}
__device__ __forceinline__ void cpa16(uint32_t s, const void* g) {
    asm volatile("cp.async.cg.shared.global [%0], [%1], 16;" :: "r"(s), "l"(g));
}
__device__ __forceinline__ void cpa_commit() {
    asm volatile("cp.async.commit_group;" ::: "memory");
}
__device__ __forceinline__ void cpa_wait0() {
    asm volatile("cp.async.wait_group 0;" ::: "memory");
}
__device__ __forceinline__ void cpa_wait1() {
    asm volatile("cp.async.wait_group 1;" ::: "memory");
}
__device__ __forceinline__ void ldsm_x4(uint32_t* r, uint32_t a) {
    asm volatile("ldmatrix.sync.aligned.m8n8.x4.shared.b16 {%0,%1,%2,%3}, [%4];"
                 : "=r"(r[0]), "=r"(r[1]), "=r"(r[2]), "=r"(r[3]) : "r"(a));
}
__device__ __forceinline__ void ldsm_x2t(uint32_t* r, uint32_t a) {
    asm volatile("ldmatrix.sync.aligned.m8n8.x2.trans.shared.b16 {%0,%1}, [%2];"
                 : "=r"(r[0]), "=r"(r[1]) : "r"(a));
}
// fp16 in, fp32 accumulate
__device__ __forceinline__ void mma16816(float* d, const uint32_t* a, const uint32_t* b) {
    asm volatile("mma.sync.aligned.m16n8k16.row.col.f32.f16.f16.f32 "
                 "{%0,%1,%2,%3}, {%4,%5,%6,%7}, {%8,%9}, {%0,%1,%2,%3};"
                 : "+f"(d[0]), "+f"(d[1]), "+f"(d[2]), "+f"(d[3])
                 : "r"(a[0]), "r"(a[1]), "r"(a[2]), "r"(a[3]), "r"(b[0]), "r"(b[1]));
}
// fp16 2-slice split: hi = rn(x), lo = rn(x - hi)
__device__ __forceinline__ void hsplit2(float x0, float x1, uint32_t& hi, uint32_t& lo) {
    __half2 h = __floats2half2_rn(x0, x1);
    float r0 = x0 - __half2float(__low2half(h));
    float r1 = x1 - __half2float(__high2half(h));
    __half2 l = __floats2half2_rn(r0, r1);
    hi = *(uint32_t*)&h;
    lo = *(uint32_t*)&l;
}

// ---------------- launch 0: routing ----------------
__global__ void k_route(const int* __restrict__ idx) {
    __shared__ int sc[NE], scur[NE];
    int tid = threadIdx.x;
    if (tid < NE) sc[tid] = 0;
    __syncthreads();
    for (int i = tid; i < NA; i += 1024) atomicAdd(&sc[idx[i]], 1);
    __syncthreads();
    if (tid == 0) {
        int s = 0;
        for (int e = 0; e < NE; e++) { g_cnt[e] = sc[e]; g_off[e] = s; scur[e] = s; s += sc[e]; }
    }
    __syncthreads();
    for (int i = tid; i < NA; i += 1024) {
        int e = idx[i];
        int p = atomicAdd(&scur[e], 1);
        g_tok[p] = i / NTK;
        g_pos[i] = p;
    }
}

// ---------------- launch 1: split X to fp16 hi/lo ----------------
__global__ void k_split_x(const float* __restrict__ hs) {
    int i = blockIdx.x * blockDim.x + threadIdx.x;
    size_t base = (size_t)i * 8;
    float4 v0 = ((const float4*)(hs + base))[0];
    float4 v1 = ((const float4*)(hs + base))[1];
    float v[8] = {v0.x, v0.y, v0.z, v0.w, v1.x, v1.y, v1.z, v1.w};
    uint32_t h[4], l[4];
#pragma unroll
    for (int p = 0; p < 4; p++) hsplit2(v[2 * p], v[2 * p + 1], h[p], l[p]);
    *(uint4*)&g_xhi[base] = make_uint4(h[0], h[1], h[2], h[3]);
    *(uint4*)&g_xlo[base] = make_uint4(l[0], l[1], l[2], l[3]);
}

// ---------------- launch 2: convert all three weight tensors to fp16 ----------------
__global__ void k_conv_w3(const float* __restrict__ wg, const float* __restrict__ wu,
                          const float* __restrict__ wd) {
    const float* src;
    uint16_t* dst;
    if (blockIdx.y == 0)      { src = wg; dst = g_wg_h; }
    else if (blockIdx.y == 1) { src = wu; dst = g_wu_h; }
    else                      { src = wd; dst = g_wd_h; }
    size_t i = (size_t)(blockIdx.x * blockDim.x + threadIdx.x) * 8;
    float4 v0 = ((const float4*)(src + i))[0];
    float4 v1 = ((const float4*)(src + i))[1];
    __half2 h0 = __floats2half2_rn(v0.x, v0.y);
    __half2 h1 = __floats2half2_rn(v0.z, v0.w);
    __half2 h2 = __floats2half2_rn(v1.x, v1.y);
    __half2 h3 = __floats2half2_rn(v1.z, v1.w);
    *(uint4*)&dst[i] = make_uint4(*(uint32_t*)&h0, *(uint32_t*)&h1,
                                  *(uint32_t*)&h2, *(uint32_t*)&h3);
}

// ---------------- launch 3: GEMM1 act = silu(X@Wg)*(X@Wu) ----------------
// CTA 128m x 64n, BK=32; A (2-slice fp16) double-buffered, B (fp16) triple-buffered.
__global__ __launch_bounds__(256, 2)
void k_gate_up() {
    const int e   = blockIdx.z;
    const int cnt = g_cnt[e];
    const int m0  = blockIdx.x * 128;
    if (m0 >= cnt) return;
    const int seg = g_off[e];
    const int c0  = blockIdx.y * 64;

    extern __shared__ char smem[];
    __shared__ int rows[128];

    const int tid = threadIdx.x;
    const int lane = tid & 31, wid = tid >> 5;
    const int wm = wid & 3, wn = wid >> 2;

    if (tid < 128) rows[tid] = (m0 + tid < cnt) ? g_tok[seg + m0 + tid] : g_tok[seg];
    __syncthreads();

    const int am = tid >> 1, ak = (tid & 1) * 16;
    const int arow = rows[am];
    const uint16_t* pxh = g_xhi + (size_t)arow * NH + ak;
    const uint16_t* pxl = g_xlo + (size_t)arow * NH + ak;

    const int half = tid >> 7;
    const int bt = tid & 127;
    const int bk = bt >> 2, bn = (bt & 3) * 16;
    const size_t boff = (size_t)e * NH * NI + (size_t)bk * NI + c0 + bn;
    const uint16_t* pbh = (half ? g_wu_h : g_wg_h) + boff;

    const uint32_t sb = smem_u32(smem);
    // A stage internal: AH 0, AL 10240.  B stage internal: GH 0, UH 4608.
    const uint32_t obh = half ? 4608u : 0u;
    const uint32_t dAh = sb + (uint32_t)(am * A_STR + ak) * 2;
    const uint32_t dAl = dAh + 10240;
    const uint32_t dBh = sb + OB1 + obh + (uint32_t)(bk * B1_STR + bn) * 2;

    float dg[2][4][4], du[2][4][4];
#pragma unroll
    for (int i = 0; i < 2; i++)
#pragma unroll
        for (int j = 0; j < 4; j++)
#pragma unroll
            for (int q = 0; q < 4; q++) { dg[i][j][q] = 0.f; du[i][j][q] = 0.f; }

#define LOADA1(st, c)                                                     \
    do {                                                                  \
        const uint16_t* _ah = pxh + (c) * 32;                             \
        const uint16_t* _al = pxl + (c) * 32;                             \
        cpa16(dAh + (st), _ah);  cpa16(dAh + (st) + 16, _ah + 8);         \
        cpa16(dAl + (st), _al);  cpa16(dAl + (st) + 16, _al + 8);         \
    } while (0)
#define LOADB1(st, c)                                                     \
    do {                                                                  \
        const uint16_t* _bh = pbh + (size_t)(c) * 32 * NI;                \
        cpa16(dBh + (st), _bh);  cpa16(dBh + (st) + 16, _bh + 8);         \
    } while (0)

    const int NC = NH / 32;
    LOADA1(0, 0);         cpa_commit();
    LOADB1(0, 0);         cpa_commit();
    LOADB1(B1STG, 1);     cpa_commit();
    cpa_wait1();          // A(0), B(0) landed (B(1) may be pending)
    __syncthreads();

    int bs = 0, bn3 = 2;   // B stage of c, B stage of c+2
    for (int c = 0; c < NC; c++) {
        const uint32_t ca = (uint32_t)(c & 1) * ASTG;
        const uint32_t cb = OB1 + (uint32_t)bs * B1STG;
        if (c + 1 < NC) { LOADA1(((c + 1) & 1) * ASTG, c + 1); cpa_commit(); }
        if (c + 2 < NC) { LOADB1((uint32_t)bn3 * B1STG, c + 2); cpa_commit(); }

#pragma unroll
        for (int ks = 0; ks < 2; ks++) {
            const int k16 = ks * 16;
            uint32_t ah[2][4], al[2][4];
#pragma unroll
            for (int i = 0; i < 2; i++) {
                int row = wm * 32 + i * 16 + (lane & 15);
                int col = k16 + (lane >> 4) * 8;
                uint32_t off = (uint32_t)(row * A_STR + col) * 2;
                ldsm_x4(ah[i], sb + ca + off);
                ldsm_x4(al[i], sb + ca + 10240 + off);
            }
#pragma unroll
            for (int j = 0; j < 4; j++) {
                int n = wn * 32 + j * 8;
                uint32_t off = (uint32_t)((k16 + (lane & 15)) * B1_STR + n) * 2;
                uint32_t gh[2], uh[2];
                ldsm_x2t(gh, sb + cb + off);
                ldsm_x2t(uh, sb + cb + 4608 + off);
                mma16816(dg[0][j], ah[0], gh);
                mma16816(dg[1][j], ah[1], gh);
                mma16816(du[0][j], ah[0], uh);
                mma16816(du[1][j], ah[1], uh);
                mma16816(dg[0][j], al[0], gh);
                mma16816(dg[1][j], al[1], gh);
                mma16816(du[0][j], al[0], uh);
                mma16816(du[1][j], al[1], uh);
            }
        }
        if (c + 2 < NC) cpa_wait1(); else cpa_wait0();
        __syncthreads();
        bs = (bs == 2) ? 0 : bs + 1;
        bn3 = (bn3 == 2) ? 0 : bn3 + 1;
    }
#undef LOADA1
#undef LOADB1

    // epilogue: silu(g)*u -> act fp16 hi/lo
#pragma unroll
    for (int i = 0; i < 2; i++)
#pragma unroll
        for (int h2 = 0; h2 < 2; h2++) {
            int m = m0 + wm * 32 + i * 16 + h2 * 8 + (lane >> 2);
            if (m < cnt) {
                size_t rowb = (size_t)(seg + m) * NI + c0 + wn * 32 + (lane & 3) * 2;
#pragma unroll
                for (int j = 0; j < 4; j++) {
                    float g0 = dg[i][j][h2 * 2], g1 = dg[i][j][h2 * 2 + 1];
                    float u0 = du[i][j][h2 * 2], u1 = du[i][j][h2 * 2 + 1];
                    float r0 = g0 / (1.f + __expf(-g0)) * u0;
                    float r1 = g1 / (1.f + __expf(-g1)) * u1;
                    uint32_t hh, ll;
                    hsplit2(r0, r1, hh, ll);
                    *(uint32_t*)&g_act_hi[rowb + j * 8] = hh;
                    *(uint32_t*)&g_act_lo[rowb + j * 8] = ll;
                }
            }
        }
}

// ---------------- launch 4: GEMM2 y = act @ Wd ----------------
// CTA 128m x 128n, BK=32; A (2-slice) double-buffered, B (fp16) triple-buffered.
__global__ __launch_bounds__(256, 2)
void k_down() {
    const int e   = blockIdx.z;
    const int cnt = g_cnt[e];
    const int m0  = blockIdx.x * 128;
    if (m0 >= cnt) return;
    const int seg = g_off[e];
    const int h0  = blockIdx.y * 128;

    extern __shared__ char smem[];

    const int tid = threadIdx.x;
    const int lane = tid & 31, wid = tid >> 5;
    const int wm = wid & 3, wn = wid >> 2;

    const int am = tid >> 1, ak = (tid & 1) * 16;
    const int aslot = seg + ((m0 + am < cnt) ? (m0 + am) : 0);
    const uint16_t* pah = g_act_hi + (size_t)aslot * NI + ak;
    const uint16_t* pal = g_act_lo + (size_t)aslot * NI + ak;

    const int bk = tid >> 3, bn = (tid & 7) * 16;
    const size_t boff = (size_t)e * NI * NH + (size_t)bk * NH + h0 + bn;
    const uint16_t* pbh = g_wd_h + boff;

    const uint32_t sb = smem_u32(smem);
    const uint32_t dAh = sb + (uint32_t)(am * A_STR + ak) * 2;
    const uint32_t dAl = dAh + 10240;
    const uint32_t dBh = sb + OB2 + (uint32_t)(bk * B2_STR + bn) * 2;

    float acc[2][8][4];
#pragma unroll
    for (int i = 0; i < 2; i++)
#pragma unroll
        for (int j = 0; j < 8; j++)
#pragma unroll
            for (int q = 0; q < 4; q++) acc[i][j][q] = 0.f;

#define LOADA2(st, c)                                                     \
    do {                                                                  \
        const uint16_t* _ah = pah + (c) * 32;                             \
        const uint16_t* _al = pal + (c) * 32;                             \
        cpa16(dAh + (st), _ah);  cpa16(dAh + (st) + 16, _ah + 8);         \
        cpa16(dAl + (st), _al);  cpa16(dAl + (st) + 16, _al + 8);         \
    } while (0)
#define LOADB2(st, c)                                                     \
    do {                                                                  \
        const uint16_t* _bh = pbh + (size_t)(c) * 32 * NH;                \
        cpa16(dBh + (st), _bh);  cpa16(dBh + (st) + 16, _bh + 8);         \
    } while (0)

    const int NC = NI / 32;
    LOADA2(0, 0);         cpa_commit();
    LOADB2(0, 0);         cpa_commit();
    LOADB2(B2STG, 1);     cpa_commit();
    cpa_wait1();
    __syncthreads();

    int bs = 0, bn3 = 2;
    for (int c = 0; c < NC; c++) {
        const uint32_t ca = (uint32_t)(c & 1) * ASTG;
        const uint32_t cb = OB2 + (uint32_t)bs * B2STG;
        if (c + 1 < NC) { LOADA2(((c + 1) & 1) * ASTG, c + 1); cpa_commit(); }
        if (c + 2 < NC) { LOADB2((uint32_t)bn3 * B2STG, c + 2); cpa_commit(); }

#pragma unroll
        for (int ks = 0; ks < 2; ks++) {
            const int k16 = ks * 16;
            uint32_t ah[2][4], al[2][4];
#pragma unroll
            for (int i = 0; i < 2; i++) {
                int row = wm * 32 + i * 16 + (lane & 15);
                int col = k16 + (lane >> 4) * 8;
                uint32_t off = (uint32_t)(row * A_STR + col) * 2;
                ldsm_x4(ah[i], sb + ca + off);
                ldsm_x4(al[i], sb + ca + 10240 + off);
            }
#pragma unroll
            for (int jp = 0; jp < 4; jp++) {
                const int j0 = jp * 2, j1 = jp * 2 + 1;
                int n0 = wn * 64 + j0 * 8, n1 = wn * 64 + j1 * 8;
                uint32_t o0 = (uint32_t)((k16 + (lane & 15)) * B2_STR + n0) * 2;
                uint32_t o1 = (uint32_t)((k16 + (lane & 15)) * B2_STR + n1) * 2;
                uint32_t bh0[2], bh1[2];
                ldsm_x2t(bh0, sb + cb + o0);
                ldsm_x2t(bh1, sb + cb + o1);
                mma16816(acc[0][j0], ah[0], bh0);
                mma16816(acc[1][j0], ah[1], bh0);
                mma16816(acc[0][j1], ah[0], bh1);
                mma16816(acc[1][j1], ah[1], bh1);
                mma16816(acc[0][j0], al[0], bh0);
                mma16816(acc[1][j0], al[1], bh0);
                mma16816(acc[0][j1], al[0], bh1);
                mma16816(acc[1][j1], al[1], bh1);
            }
        }
        if (c + 2 < NC) cpa_wait1(); else cpa_wait0();
        __syncthreads();
        bs = (bs == 2) ? 0 : bs + 1;
        bn3 = (bn3 == 2) ? 0 : bn3 + 1;
    }
#undef LOADA2
#undef LOADB2

#pragma unroll
    for (int i = 0; i < 2; i++)
#pragma unroll
        for (int h2 = 0; h2 < 2; h2++) {
            int m = m0 + wm * 32 + i * 16 + h2 * 8 + (lane >> 2);
            if (m < cnt) {
                float* op = g_y + (size_t)(seg + m) * NH + h0 + wn * 64 + (lane & 3) * 2;
#pragma unroll
                for (int j = 0; j < 8; j++)
                    *(float2*)(op + j * 8) = make_float2(acc[i][j][h2 * 2], acc[i][j][h2 * 2 + 1]);
            }
        }
}

// ---------------- launch 5: combine ----------------
__global__ void k_combine(const float* __restrict__ val, float* __restrict__ out) {
    int i = blockIdx.x * blockDim.x + threadIdx.x;
    if (i >= NT * (NH / 4)) return;
    int t  = i / (NH / 4);
    int h4 = i - t * (NH / 4);
    float4 r = make_float4(0.f, 0.f, 0.f, 0.f);
#pragma unroll
    for (int k = 0; k < NTK; k++) {
        int   p = g_pos[t * NTK + k];
        float w = val[t * NTK + k];
        float4 y = *(const float4*)&g_y[(size_t)p * NH + h4 * 4];
        r.x += w * y.x; r.y += w * y.y; r.z += w * y.z; r.w += w * y.w;
    }
    *(float4*)&out[(size_t)t * NH + h4 * 4] = r;
}

// ---------------- launch ----------------
extern "C" void kernel_launch(void* const* d_in, const int* in_sizes, int n_in,
                              void* d_out, int out_size) {
    const float* hs  = (const float*)d_in[0];
    const int*   idx = (const int*)d_in[1];
    const float* val = (const float*)d_in[2];
    const float* wg  = (const float*)d_in[3];
    const float* wu  = (const float*)d_in[4];
    const float* wd  = (const float*)d_in[5];
    float*       out = (float*)d_out;
    (void)in_sizes; (void)n_in; (void)out_size;

    const int SM1 = 2 * ASTG + 3 * B1STG;   // 68608
    const int SM2 = 2 * ASTG + 3 * B2STG;   // 67072
    cudaFuncSetAttribute(k_gate_up, cudaFuncAttributeMaxDynamicSharedMemorySize, SM1);
    cudaFuncSetAttribute(k_down,    cudaFuncAttributeMaxDynamicSharedMemorySize, SM2);

    k_route<<<1, 1024>>>(idx);                                  // 0
    k_split_x<<<NT * NH / 8 / 256, 256>>>(hs);                  // 1
    dim3 gw(NW / 8 / 256, 3);
    k_conv_w3<<<gw, 256>>>(wg, wu, wd);                         // 2

    dim3 g1(NA / 128, NI / 64, NE);                             // 3 (profiled slot)
    k_gate_up<<<g1, 256, SM1>>>();

    dim3 g2(NA / 128, NH / 128, NE);                            // 4
    k_down<<<g2, 256, SM2>>>();

    k_combine<<<(NT * (NH / 4) + 255) / 256, 256>>>(val, out);  // 5
}